// round 12
// baseline (speedup 1.0000x reference)
#include <cuda_runtime.h>

// MaskedWeight: B=256, DIM=16, H_IN=H_OUT=32, IN_F=OUT_F=512
// grid = B*8 CTAs x 256 thr, 4 CTAs/SM (<=64 regs).
// Each warp: 4 balanced row pairs (rb, 15-rb), 2-deep load pipeline.
// Per-pair partial sums (ya,yb,sA,sB) are NOT reduced inline: packed into one
// float4 STS.128 (manual spill). One end-phase per warp reduces all 4 records
// with interleaved butterflies after the loads are done -> mainloop is pure
// LDG/FMA/exp/STS -> high DRAM duty cycle at full occupancy.
// Last CTA per sample (atomicInc-wrap, graph-safe) finalizes.

#define NB 256
#define OUTF 512
#define INF 512
#define SLICES 8

__device__ float g_yraw[NB * OUTF];
__device__ float g_lse[NB * OUTF];
__device__ float g_f2[NB * SLICES];
__device__ unsigned int g_cnt[NB];   // zero-init; self-resets via atomicInc wrap

__global__ __launch_bounds__(256, 4)
void mw_fused(const float* __restrict__ inputs,     // [B, 512]
              const float* __restrict__ hyper_w,    // [B, 512, 512]
              const float* __restrict__ hyper_b,    // [B, 512]
              const float* __restrict__ lgc,        // [B, 16, 32, 1]
              const float* __restrict__ sfp,        // [1]
              float* __restrict__ out)              // [B*512 outputs | B*512 log_det]
{
    const int cta  = blockIdx.x;
    const int b    = cta >> 3;
    const int s    = cta & (SLICES - 1);
    const int tid  = threadIdx.x;
    const int warp = tid >> 5;
    const int lane = tid & 31;
    const int g    = (s << 3) + warp;   // 0..63
    const int colA = g & 31;
    const int rb0  = g >> 5;            // 0..1

    __shared__ __align__(16) float x_s[INF];
    __shared__ float lgc_s[512];
    __shared__ __align__(16) float4 red_buf[8][4][32];  // [warp][pair][lane]
    __shared__ float f2_red[8];
    __shared__ int amLast;

    x_s[tid]         = inputs[b * INF + tid];
    x_s[tid + 256]   = inputs[b * INF + tid + 256];
    lgc_s[tid]       = lgc[b * 512 + tid];
    lgc_s[tid + 256] = lgc[b * 512 + tid + 256];
    __syncthreads();

    const float*  hw = hyper_w + (size_t)b * (OUTF * INF);
    const float4* x4 = reinterpret_cast<const float4*>(x_s);

    float f2 = 0.0f;

    float4 v0[4], v1[4];
    float dA0, dB0, dA1, dB1;

    // Load one pair's data (4 predicated LDG.128 + 2 scalar LDG) into regs.
#define LOADP(K, V, DA, DB) do {                                              \
        const int rbA = rb0 + 2 * (K);                                        \
        const int rbB = 15 - rbA;                                             \
        const float* rowA = hw + (size_t)(((rbA) << 5) + colA) * INF;         \
        const float* rowB = hw + (size_t)(((rbB) << 5) + colA) * INF;         \
        const int n4a = rbA << 3;                                             \
        _Pragma("unroll")                                                     \
        for (int j = 0; j < 4; j++) {                                         \
            const int i4 = lane + 32 * j;                                     \
            const float* p = (i4 < n4a) ? rowA : rowB;                        \
            const int idx  = (i4 < n4a) ? i4 : (i4 - n4a);                    \
            float4 t = make_float4(0.f, 0.f, 0.f, 0.f);                       \
            if (i4 < 120) t = reinterpret_cast<const float4*>(p)[idx];        \
            V[j] = t;                                                         \
        }                                                                     \
        DA = rowA[(rbA << 5) + lane];                                         \
        DB = rowB[(rbB << 5) + lane];                                         \
    } while (0)

    // Consume one pair: FMAs + one STS.128 of per-lane partials. No shuffles.
#define PROCP(K, V, DA, DB) do {                                              \
        const int rbA = rb0 + 2 * (K);                                        \
        const int rbB = 15 - rbA;                                             \
        const int n4a = rbA << 3;                                             \
        float ya = 0.0f, yb = 0.0f;                                           \
        _Pragma("unroll")                                                     \
        for (int j = 0; j < 4; j++) {                                         \
            const int i4 = lane + 32 * j;                                     \
            const bool inA = (i4 < n4a);                                      \
            const int idx  = inA ? i4 : (i4 - n4a);                           \
            const float4 xv = x4[idx];                                        \
            const float4 v  = V[j];                                           \
            float dot = v.x * xv.x;                                           \
            dot = fmaf(v.y, xv.y, dot);                                       \
            dot = fmaf(v.z, xv.z, dot);                                       \
            dot = fmaf(v.w, xv.w, dot);                                       \
            f2 = fmaf(v.x, v.x, f2);                                          \
            f2 = fmaf(v.y, v.y, f2);                                          \
            f2 = fmaf(v.z, v.z, f2);                                          \
            f2 = fmaf(v.w, v.w, f2);                                          \
            if (inA) ya += dot; else yb += dot;                               \
        }                                                                     \
        const int dAc = rbA << 5, dBc = rbB << 5;                             \
        const float eA = __expf(DA), eB = __expf(DB);                         \
        ya = fmaf(eA, x_s[dAc + lane], ya);                                   \
        yb = fmaf(eB, x_s[dBc + lane], yb);                                   \
        f2 = fmaf(eA, eA, f2);                                                \
        f2 = fmaf(eB, eB, f2);                                                \
        /* max-free logsumexp terms: values are O(1), fp32-safe */            \
        const float sA = __expf(DA + lgc_s[dAc + lane]);                      \
        const float sB = __expf(DB + lgc_s[dBc + lane]);                      \
        red_buf[warp][K][lane] = make_float4(ya, yb, sA, sB);                 \
    } while (0)

    LOADP(0, v0, dA0, dB0);
    LOADP(1, v1, dA1, dB1);
    PROCP(0, v0, dA0, dB0);
    LOADP(2, v0, dA0, dB0);
    PROCP(1, v1, dA1, dB1);
    LOADP(3, v1, dA1, dB1);
    PROCP(2, v0, dA0, dB0);
    PROCP(3, v1, dA1, dB1);

#undef LOADP
#undef PROCP

    // ---- end-phase: per-warp reduction of the 4 stored records ----
    __syncwarp();
    {
        float4 r0 = red_buf[warp][0][lane];
        float4 r1 = red_buf[warp][1][lane];
        float4 r2 = red_buf[warp][2][lane];
        float4 r3 = red_buf[warp][3][lane];
        #pragma unroll
        for (int sh = 16; sh; sh >>= 1) {
            r0.x += __shfl_xor_sync(0xffffffffu, r0.x, sh);
            r0.y += __shfl_xor_sync(0xffffffffu, r0.y, sh);
            r0.z += __shfl_xor_sync(0xffffffffu, r0.z, sh);
            r0.w += __shfl_xor_sync(0xffffffffu, r0.w, sh);
            r1.x += __shfl_xor_sync(0xffffffffu, r1.x, sh);
            r1.y += __shfl_xor_sync(0xffffffffu, r1.y, sh);
            r1.z += __shfl_xor_sync(0xffffffffu, r1.z, sh);
            r1.w += __shfl_xor_sync(0xffffffffu, r1.w, sh);
            r2.x += __shfl_xor_sync(0xffffffffu, r2.x, sh);
            r2.y += __shfl_xor_sync(0xffffffffu, r2.y, sh);
            r2.z += __shfl_xor_sync(0xffffffffu, r2.z, sh);
            r2.w += __shfl_xor_sync(0xffffffffu, r2.w, sh);
            r3.x += __shfl_xor_sync(0xffffffffu, r3.x, sh);
            r3.y += __shfl_xor_sync(0xffffffffu, r3.y, sh);
            r3.z += __shfl_xor_sync(0xffffffffu, r3.z, sh);
            r3.w += __shfl_xor_sync(0xffffffffu, r3.w, sh);
        }
        float4 rr[4] = { r0, r1, r2, r3 };
        #pragma unroll
        for (int k = 0; k < 4; k++) {
            const int rbA = rb0 + 2 * k;
            const int oA  = (rbA << 5) + colA;
            const int oB  = ((15 - rbA) << 5) + colA;
            if (lane == 0) {
                g_yraw[b * OUTF + oA] = rr[k].x;
                g_lse [b * OUTF + oA] = __logf(rr[k].z);
            } else if (lane == 1) {
                g_yraw[b * OUTF + oB] = rr[k].y;
                g_lse [b * OUTF + oB] = __logf(rr[k].w);
            }
        }
    }

    // per-CTA Frobenius partial (fixed slot -> deterministic final sum)
    #pragma unroll
    for (int sh = 16; sh; sh >>= 1) f2 += __shfl_xor_sync(0xffffffffu, f2, sh);
    if (lane == 0) f2_red[warp] = f2;
    __syncthreads();
    if (tid == 0) {
        float t = 0.0f;
        #pragma unroll
        for (int w = 0; w < 8; w++) t += f2_red[w];
        g_f2[b * SLICES + s] = t;
    }

    // ---- last-CTA-per-sample finalize ----
    __threadfence();
    __syncthreads();
    if (tid == 0) {
        unsigned int old = atomicInc(&g_cnt[b], SLICES - 1);  // wraps to 0 on last
        amLast = (old == SLICES - 1);
    }
    __syncthreads();
    if (!amLast) return;
    __threadfence();

    float F2 = 0.0f;
    #pragma unroll
    for (int i = 0; i < SLICES; i++) F2 += g_f2[b * SLICES + i];

    const float sf   = sfp[0];
    const float inv  = __expf(sf) * rsqrtf(F2);
    const float base = sf - 0.5f * __logf(F2);

    #pragma unroll
    for (int r = 0; r < 2; r++) {
        const int o = tid + 256 * r;
        out[b * OUTF + o] = fmaf(g_yraw[b * OUTF + o], inv, hyper_b[b * OUTF + o]);
        out[NB * OUTF + b * 512 + o] = base + g_lse[b * 512 + o];
    }
}

extern "C" void kernel_launch(void* const* d_in, const int* in_sizes, int n_in,
                              void* d_out, int out_size) {
    const float* inputs  = (const float*)d_in[0];
    const float* hyper_w = (const float*)d_in[1];
    const float* hyper_b = (const float*)d_in[2];
    const float* lgc     = (const float*)d_in[3];
    const float* sf      = (const float*)d_in[4];
    mw_fused<<<NB * SLICES, 256>>>(inputs, hyper_w, hyper_b, lgc, sf, (float*)d_out);
}